// round 11
// baseline (speedup 1.0000x reference)
#include <cuda_runtime.h>
#include <cuda_fp16.h>
#include <cstdint>

// ---------------------------------------------------------------------------
// Problem constants
// ---------------------------------------------------------------------------
#define Dm    512
#define Hh    8
#define DHh   64
#define DFFm  2048
#define Kk    4
#define Ss    4
#define Bb    4
#define LQ    4165
#define NTOK  (Bb * LQ)     // 16660
#define MVOA  896           // merged V(512) + OFF(256) + ATT(128)
#define MOA2  384           // OFF+ATT width

__device__ __constant__ int c_wl[4]   = {56, 28, 14, 7};
__device__ __constant__ int c_hl[4]   = {56, 28, 14, 7};
__device__ __constant__ int c_offs[4] = {0, 3136, 3920, 4116};

// ---------------------------------------------------------------------------
// Scratch
// ---------------------------------------------------------------------------
__device__ float g_REF [(size_t)NTOK * 2];
__device__ float g_OA  [(size_t)NTOK * MOA2];   // OFF | ATT logits (fp32)
__device__ float g_ball[MVOA];

// fp16 buffers
__device__ __half g_Qh  [(size_t)NTOK * Dm];
__device__ __half g_Vh  [(size_t)NTOK * Dm];
__device__ __half g_ACCh[(size_t)NTOK * Dm];
__device__ __half g_A2h [(size_t)NTOK * Dm];
__device__ __half g_Xh  [(size_t)NTOK * Dm];
__device__ __half g_Hbh [(size_t)NTOK * DFFm];
__device__ __half g_Yh  [(size_t)NTOK * Dm];
__device__ __half g_Wah [(size_t)Dm * MVOA];
__device__ __half g_Woh [(size_t)Dm * Dm];
__device__ __half g_W1h [(size_t)Dm * DFFm];
__device__ __half g_W2h [(size_t)DFFm * Dm];

// ---------------------------------------------------------------------------
__device__ __forceinline__ int scale_of(int p, int& loc) {
    if (p < 3136)      { loc = p;        return 0; }
    else if (p < 3920) { loc = p - 3136; return 1; }
    else if (p < 4116) { loc = p - 3920; return 2; }
    else               { loc = p - 4116; return 3; }
}

// ---------------------------------------------------------------------------
// pack: srcs -> Qh fp16; refs -> REF (folded: first NTOK threads copy REF)
// ---------------------------------------------------------------------------
__global__ void pack_kernel(const float* __restrict__ s0, const float* __restrict__ s1,
                            const float* __restrict__ s2, const float* __restrict__ s3,
                            const float* __restrict__ r0, const float* __restrict__ r1,
                            const float* __restrict__ r2, const float* __restrict__ r3,
                            __half* __restrict__ Qh, float* __restrict__ REF)
{
    int e = blockIdx.x * blockDim.x + threadIdx.x;
    const int total = NTOK * (Dm / 4);
    if (e >= total) return;
    int n  = e >> 7;
    int d4 = e & 127;
    int b = n / LQ;
    int p = n % LQ;
    int loc;
    int l = scale_of(p, loc);
    const float* src = (l == 0) ? s0 : (l == 1) ? s1 : (l == 2) ? s2 : s3;
    int lq = c_wl[l] * c_hl[l];
    float4 v = reinterpret_cast<const float4*>(src)[(size_t)(b * lq + loc) * 128 + d4];
    __half h[4] = {__float2half(v.x), __float2half(v.y), __float2half(v.z), __float2half(v.w)};
    *reinterpret_cast<uint2*>(Qh + (size_t)n * Dm + d4 * 4) = *reinterpret_cast<uint2*>(h);

    if (e < NTOK) {
        int nb = e / LQ, pp = e % LQ, lc;
        int ll = scale_of(pp, lc);
        const float* rsrc = (ll == 0) ? r0 : (ll == 1) ? r1 : (ll == 2) ? r2 : r3;
        int lq2 = c_wl[ll] * c_hl[ll];
        float2 rv = *reinterpret_cast<const float2*>(rsrc + (size_t)(nb * lq2 + lc) * 2);
        *reinterpret_cast<float2*>(REF + (size_t)e * 2) = rv;
    }
}

// merge Wv/Woff/Wattn -> fp16 [512, 896] (+ merged fp32 bias)
__global__ void merge_h_kernel(const float* __restrict__ Wv, const float* __restrict__ Woff,
                               const float* __restrict__ Wattn,
                               const float* __restrict__ bv, const float* __restrict__ boff,
                               const float* __restrict__ battn,
                               __half* __restrict__ Wah, float* __restrict__ ball)
{
    int i = blockIdx.x * blockDim.x + threadIdx.x;
    if (i < Dm * MVOA) {
        int r = i / MVOA, c = i % MVOA;
        float w;
        if (c < 512)       w = Wv[r * 512 + c];
        else if (c < 768)  w = Woff[r * 256 + (c - 512)];
        else               w = Wattn[r * 128 + (c - 768)];
        Wah[i] = __float2half(w);
    }
    if (i < MVOA)
        ball[i] = (i < 512) ? bv[i] : (i < 768) ? boff[i - 512] : battn[i - 768];
}

// single kernel converting W1, W2, Wo -> fp16
#define N_W1 (Dm * DFFm)
#define N_W2 (DFFm * Dm)
#define N_WO (Dm * Dm)
__global__ void conv_all_kernel(const float* __restrict__ W1, const float* __restrict__ W2,
                                const float* __restrict__ Wo,
                                __half* __restrict__ W1h, __half* __restrict__ W2h,
                                __half* __restrict__ Woh)
{
    int i = blockIdx.x * blockDim.x + threadIdx.x;
    if (i < N_W1)                    W1h[i] = __float2half(W1[i]);
    else if (i < N_W1 + N_W2)        W2h[i - N_W1] = __float2half(W2[i - N_W1]);
    else if (i < N_W1 + N_W2 + N_WO) Woh[i - N_W1 - N_W2] = __float2half(Wo[i - N_W1 - N_W2]);
}

// ---------------------------------------------------------------------------
// fp16 GEMM via mma.sync.m16n8k16.f32.f16.f16.f32, 4-stage cp.async pipeline.
// MODE 0: fp32 out. MODE 1: relu -> fp16. MODE 3: fp16 (no relu).
// MODE 2: colBase<512 -> fp16 to Vh; else fp32 to OA.
// ---------------------------------------------------------------------------
#define LDSM4(r, addr) \
    asm volatile("ldmatrix.sync.aligned.m8n8.x4.shared.b16 {%0,%1,%2,%3}, [%4];" \
                 : "=r"((r)[0]), "=r"((r)[1]), "=r"((r)[2]), "=r"((r)[3]) : "r"(addr))
#define LDSM4T(r, addr) \
    asm volatile("ldmatrix.sync.aligned.m8n8.x4.trans.shared.b16 {%0,%1,%2,%3}, [%4];" \
                 : "=r"((r)[0]), "=r"((r)[1]), "=r"((r)[2]), "=r"((r)[3]) : "r"(addr))
#define MMA16816H(c, a, b) \
    asm volatile("mma.sync.aligned.m16n8k16.row.col.f32.f16.f16.f32 " \
                 "{%0,%1,%2,%3}, {%4,%5,%6,%7}, {%8,%9}, {%0,%1,%2,%3};" \
                 : "+f"((c)[0]), "+f"((c)[1]), "+f"((c)[2]), "+f"((c)[3]) \
                 : "r"((a)[0]), "r"((a)[1]), "r"((a)[2]), "r"((a)[3]), \
                   "r"((b)[0]), "r"((b)[1]))

#define STAGE_BYTES 18944            // 10240 (A) + 8704 (B)
#define SMEM_GEMM   (4 * STAGE_BYTES)

template<int MODE>
__global__ __launch_bounds__(256, 2)
void gemm_fp16_kernel(const __half* __restrict__ A,
                      const __half* __restrict__ W,
                      const float* __restrict__ bias, void* __restrict__ Cout,
                      void* __restrict__ Cout2,
                      int N, int K, int M)
{
    extern __shared__ char smem[];
    const uint32_t sdata = (uint32_t)__cvta_generic_to_shared(smem);

    const int tid  = threadIdx.x;
    const int lane = tid & 31;
    const int wid  = tid >> 5;
    const int wm = (wid & 1) * 64;
    const int wn = (wid >> 1) * 32;
    const int rowBase = blockIdx.y * 128;
    const int colBase = blockIdx.x * 128;

    const int lrowA = lane & 15;
    const int lcolA = (lane >> 4) * 8;
    const uint32_t aFragOff = (uint32_t)((wm + lrowA) * 80 + lcolA * 2);
    const int grp = lane >> 3;
    const int rB  = lane & 7;
    const uint32_t bFragOff = (uint32_t)(10240 + ((grp & 1) * 8 + rB) * 272 + (grp >> 1) * 16 + wn * 2);

    const int T = K >> 5;

    float acc[4][4][4];
#pragma unroll
    for (int i = 0; i < 4; i++)
#pragma unroll
        for (int j = 0; j < 4; j++)
#pragma unroll
            for (int r = 0; r < 4; r++) acc[i][j][r] = 0.f;

    auto loadStage = [&](int t, int stage) {
        int kp0 = t << 5;
        uint32_t sb = sdata + stage * STAGE_BYTES;
#pragma unroll
        for (int i = 0; i < 2; i++) {
            int id = tid * 2 + i;
            int r = id >> 2, c = id & 3;
            int gr = rowBase + r;
            const void* src = (const void*)(A + (size_t)gr * K + kp0 + c * 8);
            uint32_t dst = sb + r * 80 + c * 16;
            int sz = (gr < N) ? 16 : 0;
            asm volatile("cp.async.cg.shared.global [%0], [%1], 16, %2;"
                         :: "r"(dst), "l"(src), "r"(sz));
        }
#pragma unroll
        for (int i = 0; i < 2; i++) {
            int id = tid * 2 + i;
            int r = id >> 4, c = id & 15;
            const void* src = (const void*)(W + (size_t)(kp0 + r) * M + colBase + c * 8);
            uint32_t dst = sb + 10240 + r * 272 + c * 16;
            asm volatile("cp.async.cg.shared.global [%0], [%1], 16;"
                         :: "r"(dst), "l"(src));
        }
        asm volatile("cp.async.commit_group;" ::: "memory");
    };

    loadStage(0, 0);
    if (T > 1) loadStage(1, 1);
    if (T > 2) loadStage(2, 2);

    for (int t = 0; t < T; t++) {
        int rem = T - 1 - t;
        if (rem >= 2)      asm volatile("cp.async.wait_group 2;" ::: "memory");
        else if (rem == 1) asm volatile("cp.async.wait_group 1;" ::: "memory");
        else               asm volatile("cp.async.wait_group 0;" ::: "memory");
        __syncthreads();

        if (t + 3 < T) loadStage(t + 3, (t + 3) & 3);

        uint32_t sb = sdata + (t & 3) * STAGE_BYTES;
        uint32_t aBase = sb + aFragOff;
        uint32_t bBase = sb + bFragOff;
#pragma unroll
        for (int ks = 0; ks < 2; ks++) {
            uint32_t af[4][4];
            uint32_t bfr[4][2];
            uint32_t aB = aBase + ks * 32;
            uint32_t bB = bBase + ks * 4352;
#pragma unroll
            for (int mt = 0; mt < 4; mt++) LDSM4(af[mt], aB + mt * 1280);
#pragma unroll
            for (int np = 0; np < 2; np++) {
                uint32_t r4[4];
                LDSM4T(r4, bB + np * 32);
                bfr[np * 2][0] = r4[0]; bfr[np * 2][1] = r4[1];
                bfr[np * 2 + 1][0] = r4[2]; bfr[np * 2 + 1][1] = r4[3];
            }
#pragma unroll
            for (int mt = 0; mt < 4; mt++)
#pragma unroll
                for (int nt = 0; nt < 4; nt++)
                    MMA16816H(acc[mt][nt], af[mt], bfr[nt]);
        }
    }

    // epilogue
    const int mr = lane >> 2;
    const int nc = (lane & 3) * 2;
    const bool vpart = (MODE == 2) && (colBase < 512);

#pragma unroll
    for (int mt = 0; mt < 4; mt++) {
#pragma unroll
        for (int nt = 0; nt < 4; nt++) {
            int n0 = colBase + wn + nt * 8 + nc;
            float bb0 = bias[n0], bb1 = bias[n0 + 1];
#pragma unroll
            for (int half = 0; half < 2; half++) {
                int m = rowBase + wm + mt * 16 + mr + half * 8;
                if (m >= N) continue;
                float v0 = acc[mt][nt][half * 2 + 0] + bb0;
                float v1 = acc[mt][nt][half * 2 + 1] + bb1;
                if (MODE == 0) {
                    *reinterpret_cast<float2*>((float*)Cout + (size_t)m * M + n0) = make_float2(v0, v1);
                } else if (MODE == 1 || MODE == 3) {
                    if (MODE == 1) { v0 = fmaxf(v0, 0.f); v1 = fmaxf(v1, 0.f); }
                    __half2 hv; hv.x = __float2half(v0); hv.y = __float2half(v1);
                    *reinterpret_cast<__half2*>((__half*)Cout + (size_t)m * M + n0) = hv;
                } else {
                    if (vpart) {
                        __half2 hv; hv.x = __float2half(v0); hv.y = __float2half(v1);
                        *reinterpret_cast<__half2*>((__half*)Cout + (size_t)m * Dm + n0) = hv;
                    } else {
                        *reinterpret_cast<float2*>((float*)Cout2 + (size_t)m * MOA2 + (n0 - 512)) = make_float2(v0, v1);
                    }
                }
            }
        }
    }
}

// ---------------------------------------------------------------------------
// Deformable sampling with fused softmax, BRANCHLESS gathers.
// One warp per (token, head); lane handles d = 2*lane, 2*lane+1.
// All 64 corner loads issue unconditionally (clamped idx, zeroed weight) so
// the memory pipeline sees maximal MLP.
// ---------------------------------------------------------------------------
__global__ void sample_kernel(const __half* __restrict__ Vh, const float* __restrict__ OA,
                              const float* __restrict__ REF, __half* __restrict__ ACCh)
{
    int wid = blockIdx.x * (blockDim.x / 32) + (threadIdx.x / 32);
    if (wid >= NTOK * Hh) return;
    int lane = threadIdx.x & 31;
    int n = wid / Hh;
    int h = wid % Hh;
    int b = n / LQ;

    float refx = REF[(size_t)n * 2 + 0];
    float refy = REF[(size_t)n * 2 + 1];
    const float* offp = OA + (size_t)n * MOA2 + h * 32;          // this head's 16 (x,y) offsets
    const float* attp = OA + (size_t)n * MOA2 + 256 + h * 16;

    // preload all offsets (32 floats) and logits (16 floats)
    float off[32];
#pragma unroll
    for (int i = 0; i < 32; i += 4) {
        float4 o4 = *reinterpret_cast<const float4*>(offp + i);
        off[i] = o4.x; off[i + 1] = o4.y; off[i + 2] = o4.z; off[i + 3] = o4.w;
    }
    float lg[16], mx = -1e30f;
#pragma unroll
    for (int i = 0; i < 16; i += 4) {
        float4 l4 = *reinterpret_cast<const float4*>(attp + i);
        lg[i] = l4.x; lg[i + 1] = l4.y; lg[i + 2] = l4.z; lg[i + 3] = l4.w;
    }
#pragma unroll
    for (int i = 0; i < 16; i++) mx = fmaxf(mx, lg[i]);
    float ssum = 0.f;
#pragma unroll
    for (int i = 0; i < 16; i++) { lg[i] = expf(lg[i] - mx); ssum += lg[i]; }
    float sinv = 1.f / ssum;

    float acc0 = 0.f, acc1 = 0.f;

#pragma unroll
    for (int s = 0; s < Ss; s++) {
        const int wl = c_wl[s], hl = c_hl[s];
        const int base_tok = b * LQ + c_offs[s];
        const float fwl = (float)wl, fhl = (float)hl;
#pragma unroll
        for (int k = 0; k < Kk; k++) {
            float w  = lg[s * 4 + k] * sinv;
            float x = refx * fwl + off[(s * 4 + k) * 2 + 0] - 0.5f;
            float y = refy * fhl + off[(s * 4 + k) * 2 + 1] - 0.5f;
            float x0f = floorf(x), y0f = floorf(y);
            int x0 = (int)x0f, y0 = (int)y0f;
            float wx1 = x - x0f, wx0 = 1.f - wx1;
            float wy1 = y - y0f, wy0 = 1.f - wy1;

            // per-corner clamped index + masked weight (branchless)
            int x0c = min(max(x0, 0), wl - 1);
            int x1c = min(max(x0 + 1, 0), wl - 1);
            int y0c = min(max(y0, 0), hl - 1);
            int y1c = min(max(y0 + 1, 0), hl - 1);
            float vx0 = (x0 >= 0 && x0 < wl) ? 1.f : 0.f;
            float vx1 = (x0 + 1 >= 0 && x0 + 1 < wl) ? 1.f : 0.f;
            float vy0 = (y0 >= 0 && y0 < hl) ? 1.f : 0.f;
            float vy1 = (y0 + 1 >= 0 && y0 + 1 < hl) ? 1.f : 0.f;

            const __half2* p00 = reinterpret_cast<const __half2*>(
                Vh + ((size_t)(base_tok + y0c * wl + x0c) * Dm + h * DHh)) + lane;
            const __half2* p01 = reinterpret_cast<const __half2*>(
                Vh + ((size_t)(base_tok + y0c * wl + x1c) * Dm + h * DHh)) + lane;
            const __half2* p10 = reinterpret_cast<const __half2*>(
                Vh + ((size_t)(base_tok + y1c * wl + x0c) * Dm + h * DHh)) + lane;
            const __half2* p11 = reinterpret_cast<const __half2*>(
                Vh + ((size_t)(base_tok + y1c * wl + x1c) * Dm + h * DHh)) + lane;

            __half2 h00 = __ldg(p00);
            __half2 h01 = __ldg(p01);
            __half2 h10 = __ldg(p10);
            __half2 h11 = __ldg(p11);

            float w00 = w * wx0 * wy0 * vx0 * vy0;
            float w01 = w * wx1 * wy0 * vx1 * vy0;
            float w10 = w * wx0 * wy1 * vx0 * vy1;
            float w11 = w * wx1 * wy1 * vx1 * vy1;

            float2 f00 = __half22float2(h00);
            float2 f01 = __half22float2(h01);
            float2 f10 = __half22float2(h10);
            float2 f11 = __half22float2(h11);

            acc0 = fmaf(w00, f00.x, fmaf(w01, f01.x, fmaf(w10, f10.x, fmaf(w11, f11.x, acc0))));
            acc1 = fmaf(w00, f00.y, fmaf(w01, f01.y, fmaf(w10, f10.y, fmaf(w11, f11.y, acc1))));
        }
    }
    size_t base = (size_t)n * Dm + h * DHh;
    __half2 hv; hv.x = __float2half(acc0); hv.y = __float2half(acc1);
    *reinterpret_cast<__half2*>(ACCh + base + 2 * lane) = hv;
}

// ---------------------------------------------------------------------------
// Fused residual-add + LayerNorm, fp16 inputs; fp16 and/or fp32 outputs.
// ---------------------------------------------------------------------------
__global__ void add_layernorm_h_kernel(const __half* __restrict__ A, const __half* __restrict__ Bv,
                                       const float* __restrict__ g, const float* __restrict__ be,
                                       __half* __restrict__ outh, float* __restrict__ outf)
{
    int n = blockIdx.x;
    int t = threadIdx.x;
    float v[4];
    float s = 0.f, ss = 0.f;
    const __half2* a2 = reinterpret_cast<const __half2*>(A + (size_t)n * Dm);
    const __half2* b2 = reinterpret_cast<const __half2*>(Bv + (size_t)n * Dm);
#pragma unroll
    for (int i = 0; i < 2; i++) {
        int d2 = t + i * 128;
        float2 fa = __half22float2(a2[d2]);
        float2 fb = __half22float2(b2[d2]);
        float x0 = fa.x + fb.x, x1 = fa.y + fb.y;
        v[i * 2] = x0; v[i * 2 + 1] = x1;
        s += x0 + x1; ss += x0 * x0 + x1 * x1;
    }
#pragma unroll
    for (int o = 16; o > 0; o >>= 1) {
        s  += __shfl_xor_sync(0xffffffffu, s,  o);
        ss += __shfl_xor_sync(0xffffffffu, ss, o);
    }
    __shared__ float sh[8];
    int w = t >> 5, ln = t & 31;
    if (ln == 0) { sh[w] = s; sh[4 + w] = ss; }
    __syncthreads();
    float ts  = sh[0] + sh[1] + sh[2] + sh[3];
    float tss = sh[4] + sh[5] + sh[6] + sh[7];
    float mu  = ts * (1.f / Dm);
    float var = tss * (1.f / Dm) - mu * mu;
    float inv = rsqrtf(var + 1e-5f);
#pragma unroll
    for (int i = 0; i < 2; i++) {
        int d2 = t + i * 128;
        int d = d2 * 2;
        float o0 = (v[i * 2]     - mu) * inv * g[d]     + be[d];
        float o1 = (v[i * 2 + 1] - mu) * inv * g[d + 1] + be[d + 1];
        if (outh) {
            __half2 hv; hv.x = __float2half(o0); hv.y = __float2half(o1);
            *reinterpret_cast<__half2*>(outh + (size_t)n * Dm + d) = hv;
        }
        if (outf) {
            *reinterpret_cast<float2*>(outf + (size_t)n * Dm + d) = make_float2(o0, o1);
        }
    }
}

// ---------------------------------------------------------------------------
// Launch
// ---------------------------------------------------------------------------
extern "C" void kernel_launch(void* const* d_in, const int* in_sizes, int n_in,
                              void* d_out, int out_size)
{
    const float* srcs[4] = {nullptr, nullptr, nullptr, nullptr};
    const float* refs[4] = {nullptr, nullptr, nullptr, nullptr};
    const int src_sz[4] = {Bb * 56 * 56 * Dm, Bb * 28 * 28 * Dm, Bb * 14 * 14 * Dm, Bb * 7 * 7 * Dm};
    const int ref_sz[4] = {Bb * 56 * 56 * 2,  Bb * 28 * 28 * 2,  Bb * 14 * 14 * 2,  Bb * 7 * 7 * 2};
    for (int i = 0; i < 8; i++) {
        int sz = in_sizes[i];
        for (int l = 0; l < 4; l++) {
            if (sz == src_sz[l] && !srcs[l]) { srcs[l] = (const float*)d_in[i]; goto next; }
        }
        for (int l = 0; l < 4; l++) {
            if (sz == ref_sz[l] && !refs[l]) { refs[l] = (const float*)d_in[i]; goto next; }
        }
    next:;
    }

    const float* Wv    = (const float*)d_in[8];
    const float* bv    = (const float*)d_in[9];
    const float* Woff  = (const float*)d_in[10];
    const float* boff  = (const float*)d_in[11];
    const float* Wattn = (const float*)d_in[12];
    const float* battn = (const float*)d_in[13];
    const float* Wo    = (const float*)d_in[14];
    const float* bo    = (const float*)d_in[15];
    const float* W1    = (const float*)d_in[16];
    const float* b1    = (const float*)d_in[17];
    const float* W2    = (const float*)d_in[18];
    const float* b2    = (const float*)d_in[19];
    const float* g1    = (const float*)d_in[20];
    const float* be1   = (const float*)d_in[21];
    const float* g2    = (const float*)d_in[22];
    const float* be2   = (const float*)d_in[23];
    float* out = (float*)d_out;

    float *REF, *OA, *ball;
    __half *Qh, *Vh, *ACCh, *A2h, *Xh, *Hbh, *Yh, *Wah, *Woh, *W1h, *W2h;
    cudaGetSymbolAddress((void**)&REF,  g_REF);
    cudaGetSymbolAddress((void**)&OA,   g_OA);
    cudaGetSymbolAddress((void**)&ball, g_ball);
    cudaGetSymbolAddress((void**)&Qh,   g_Qh);
    cudaGetSymbolAddress((void**)&Vh,   g_Vh);
    cudaGetSymbolAddress((void**)&ACCh, g_ACCh);
    cudaGetSymbolAddress((void**)&A2h,  g_A2h);
    cudaGetSymbolAddress((void**)&Xh,   g_Xh);
    cudaGetSymbolAddress((void**)&Hbh,  g_Hbh);
    cudaGetSymbolAddress((void**)&Yh,   g_Yh);
    cudaGetSymbolAddress((void**)&Wah,  g_Wah);
    cudaGetSymbolAddress((void**)&Woh,  g_Woh);
    cudaGetSymbolAddress((void**)&W1h,  g_W1h);
    cudaGetSymbolAddress((void**)&W2h,  g_W2h);

    cudaFuncSetAttribute(gemm_fp16_kernel<0>, cudaFuncAttributeMaxDynamicSharedMemorySize, SMEM_GEMM);
    cudaFuncSetAttribute(gemm_fp16_kernel<1>, cudaFuncAttributeMaxDynamicSharedMemorySize, SMEM_GEMM);
    cudaFuncSetAttribute(gemm_fp16_kernel<2>, cudaFuncAttributeMaxDynamicSharedMemorySize, SMEM_GEMM);
    cudaFuncSetAttribute(gemm_fp16_kernel<3>, cudaFuncAttributeMaxDynamicSharedMemorySize, SMEM_GEMM);

    const int rowBlocks = (NTOK + 127) / 128;   // 131
    dim3 blk(256);

    // 0: merged VOA weight
    merge_h_kernel<<<(Dm * MVOA + 255) / 256, 256>>>(Wv, Woff, Wattn, bv, boff, battn, Wah, ball);
    // 1: all other weight converts (one kernel)
    {
        int total = N_W1 + N_W2 + N_WO;
        conv_all_kernel<<<(total + 255) / 256, 256>>>(W1, W2, Wo, W1h, W2h, Woh);
    }
    // 2: pack (Q + REF folded)
    {
        int total = NTOK * (Dm / 4);
        pack_kernel<<<(total + 255) / 256, 256>>>(srcs[0], srcs[1], srcs[2], srcs[3],
                                                  refs[0], refs[1], refs[2], refs[3], Qh, REF);
    }
    // 3: [Vh | OA] = Q @ [Wv|Woff|Wattn] + bias
    gemm_fp16_kernel<2><<<dim3(MVOA / 128, rowBlocks), blk, SMEM_GEMM>>>(Qh, Wah, ball, Vh, OA, NTOK, Dm, MVOA);
    // 4: sampling (fused softmax, branchless) -> ACCh
    {
        int warps = NTOK * Hh;
        sample_kernel<<<(warps + 7) / 8, 256>>>(Vh, OA, REF, ACCh);
    }
    // 5: A2h = ACC @ Wo + bo  (fp16 out)
    gemm_fp16_kernel<3><<<dim3(Dm / 128, rowBlocks), blk, SMEM_GEMM>>>(ACCh, Woh, bo, A2h, nullptr, NTOK, Dm, Dm);
    // 6: Xh = LN(Qh + A2h)
    add_layernorm_h_kernel<<<NTOK, 128>>>(Qh, A2h, g1, be1, Xh, nullptr);
    // 7: Hbh = fp16(relu(X @ W1 + b1))
    gemm_fp16_kernel<1><<<dim3(DFFm / 128, rowBlocks), blk, SMEM_GEMM>>>(Xh, W1h, b1, Hbh, nullptr, NTOK, Dm, DFFm);
    // 8: Yh = Hb @ W2 + b2  (fp16 out)
    gemm_fp16_kernel<3><<<dim3(Dm / 128, rowBlocks), blk, SMEM_GEMM>>>(Hbh, W2h, b2, Yh, nullptr, NTOK, DFFm, Dm);
    // 9: out = LN(Xh + Yh)  (fp32 to d_out)
    add_layernorm_h_kernel<<<NTOK, 128>>>(Xh, Yh, g2, be2, nullptr, out);
}